// round 16
// baseline (speedup 1.0000x reference)
#include <cuda_runtime.h>
#include <cuda_fp16.h>

#define NN 100000
#define NE 1600000
#define NG 256
#define ND 64
#define NH 128
#define VOCAB 128
#define TROWS 10002
#define TGROUP 16
#define SB 512
#define NB 196
#define NBT ((TROWS + TGROUP - 1) / TGROUP)
#define LOG2E 1.4426950408889634f
#define LN2   0.6931471805599453f
#define EBLK 3125   // edge-kernel blocks (8 warps each, ~4 nodes/warp)

typedef unsigned long long u64;
typedef unsigned int u32;

__device__ float   g_x[NN * ND];
__device__ uint2   g_Aq[NN * 32];
__device__ uint2   g_Bq[NN * 32];
__device__ float   g_h1[NN * NH];
__device__ int     g_deg[NN];
__device__ int     g_off[NN + 1];
__device__ int     g_pos[NN];
__device__ int4    g_e12v[NE / 2];
__device__ int4    g_e0v[NE / 2];
__device__ uint2   g_tabq[3 * TROWS * 32];
__device__ uint2   g_A0q[VOCAB * 32];
__device__ uint2   g_B0t[VOCAB * 32];
__device__ int     g_bsum[256];
__device__ float   g_sums[NG];
__device__ float   g_cnt[NG];

__device__ __forceinline__ u64 pk2(float x, float y) {
    u64 r; asm("mov.b64 %0,{%1,%2};" : "=l"(r) : "f"(x), "f"(y)); return r;
}
__device__ __forceinline__ u64 pkd(float x) { return pk2(x, x); }
__device__ __forceinline__ void upk2(u64 v, float& x, float& y) {
    asm("mov.b64 {%0,%1},%2;" : "=f"(x), "=f"(y) : "l"(v));
}
__device__ __forceinline__ u64 fma2(u64 a, u64 b, u64 c) {
    u64 d; asm("fma.rn.f32x2 %0,%1,%2,%3;" : "=l"(d) : "l"(a), "l"(b), "l"(c)); return d;
}
__device__ __forceinline__ __half2 u2h(u32 u) {
    __half2 h; *reinterpret_cast<u32*>(&h) = u; return h;
}
__device__ __forceinline__ u32 h2u(__half2 h) {
    return *reinterpret_cast<u32*>(&h);
}
__device__ __forceinline__ __half2 tanh_h2(__half2 x) {
    u32 out, in = h2u(x);
    asm("tanh.approx.f16x2 %0,%1;" : "=r"(out) : "r"(in));
    return u2h(out);
}
__device__ __forceinline__ __half2 ex2_h2(__half2 x) {
    u32 out, in = h2u(x);
    asm("ex2.approx.f16x2 %0,%1;" : "=r"(out) : "r"(in));
    return u2h(out);
}
__device__ __forceinline__ float warp_sum(float v) {
#pragma unroll
    for (int o = 16; o > 0; o >>= 1) v += __shfl_xor_sync(0xffffffffu, v, o);
    return v;
}
__device__ __forceinline__ float softplusf_(float x) {
    return fmaxf(x, 0.0f) + __logf(1.0f + __expf(-fabsf(x)));
}
__device__ __forceinline__ int tabrow_f(float dc) {
    int r = __float2int_rn((dc - 1.0f) * 2000.0f);
    return min(max(r, 0), TROWS - 1);
}
// SIMD gate, s-channels pre-scaled by log2e (ln2 restored per node)
__device__ __forceinline__ void gate1(uint2 aaq, uint2 Bv, uint2 Cv,
                                      float& m0, float& m1) {
    const __half2 h05 = __float2half2_rn(0.5f);
    const __half2 c3 = __float2half2_rn(-0.1066667f);
    const __half2 c2 = __float2half2_rn(0.3672997f);
    const __half2 c1 = __float2half2_rn(-0.7033311f);
    const __half2 c0 = __float2half2_rn(1.4426950f);
    const __half2 hz = __float2half2_rn(0.0f);
    __half2 pf = __hadd2(__hadd2(u2h(Bv.x), u2h(Cv.x)), u2h(aaq.x));
    __half2 ps = __hadd2(__hadd2(u2h(Bv.y), u2h(Cv.y)), u2h(aaq.y));
    __half2 sg = __hfma2(tanh_h2(pf), h05, h05);
    __half2 t = ex2_h2(__hneg2(__habs2(ps)));
    __half2 p = __hfma2(t, __hfma2(t, __hfma2(t, c3, c2), c1), c0);
    __half2 sp = __hfma2(t, p, __hmax2(ps, hz));
    float2 pr = __half22float2(__hmul2(sg, sp));
    m0 += pr.x; m1 += pr.y;
}

// ---- fused pre kernel: 3 conv tables + vocab transform + zero-init ----
__global__ void __launch_bounds__(256) k_pre(
    const float* __restrict__ emb,
    const float* __restrict__ Wf, const float* __restrict__ Ws,
    const float* __restrict__ bf, const float* __restrict__ bs) {
    int b = blockIdx.x;
    int tid = threadIdx.x;
    if (b < 3 * NBT) {
        int conv = b / NBT;
        int rbase = (b % NBT) * TGROUP;
        const float* Wef = Wf + conv * 192 * 64 + 128 * 64;
        const float* Wes = Ws + conv * 192 * 64 + 128 * 64;
        __shared__ float4 sW[64 * 32];
        __shared__ float  sw[TGROUP * 64];
        for (int e = tid; e < 2048; e += 256) {
            int k = e >> 5, j = e & 31;
            sW[e] = make_float4(Wef[k * 64 + j], Wes[k * 64 + j],
                                Wef[k * 64 + j + 32], Wes[k * 64 + j + 32]);
        }
        for (int e = tid; e < TGROUP * 64; e += 256) {
            int r = e >> 6, k = e & 63;
            float d = 1.0f + (float)(rbase + r) * 0.0005f;
            float c = 1.0f + (float)k * (5.0f / 63.0f);
            float t = (d - c) * (64.0f / 5.0f);
            sw[e] = __expf(-0.5f * t * t);
        }
        __syncthreads();
#pragma unroll
        for (int it = 0; it < 2; it++) {
            int idx = it * 256 + tid;
            int r = idx >> 5, j = idx & 31;
            int row = rbase + r;
            if (row >= TROWS) continue;
            float c0v = 0.0f, c1v = 0.0f, c2v = 0.0f, c3v = 0.0f;
#pragma unroll 8
            for (int k = 0; k < 64; k++) {
                float wk = sw[r * 64 + k];
                float4 wv = sW[k * 32 + j];
                c0v += wk * wv.x; c1v += wk * wv.y;
                c2v += wk * wv.z; c3v += wk * wv.w;
            }
            uint2 o;
            o.x = h2u(__floats2half2_rn(0.5f * c0v, 0.5f * c2v));
            o.y = h2u(__floats2half2_rn(LOG2E * c1v, LOG2E * c3v));
            g_tabq[(conv * TROWS + row) * 32 + j] = o;
        }
    } else if (b < 3 * NBT + 16) {
        int lane = tid & 31, w = tid >> 5;
        int v = (b - 3 * NBT) * 8 + w;
        if (v >= VOCAB) return;
        float x0 = emb[v * 64 + lane], x1 = emb[v * 64 + lane + 32];
        float af0 = bf[lane], as0 = bs[lane], af1 = bf[lane + 32], as1 = bs[lane + 32];
        float gf0 = 0.0f, gs0 = 0.0f, gf1 = 0.0f, gs1 = 0.0f;
#pragma unroll 8
        for (int k = 0; k < 64; k++) {
            float xv = __shfl_sync(0xffffffffu, (k < 32) ? x0 : x1, k & 31);
            af0 += xv * Wf[k * 64 + lane];
            as0 += xv * Ws[k * 64 + lane];
            af1 += xv * Wf[k * 64 + lane + 32];
            as1 += xv * Ws[k * 64 + lane + 32];
            gf0 += xv * Wf[(64 + k) * 64 + lane];
            gs0 += xv * Ws[(64 + k) * 64 + lane];
            gf1 += xv * Wf[(64 + k) * 64 + lane + 32];
            gs1 += xv * Ws[(64 + k) * 64 + lane + 32];
        }
        uint2 oa;
        oa.x = h2u(__floats2half2_rn(0.5f * af0, 0.5f * af1));
        oa.y = h2u(__floats2half2_rn(LOG2E * as0, LOG2E * as1));
        g_A0q[v * 32 + lane] = oa;
        uint2 o;
        o.x = h2u(__floats2half2_rn(0.5f * gf0, 0.5f * gf1));
        o.y = h2u(__floats2half2_rn(LOG2E * gs0, LOG2E * gs1));
        g_B0t[v * 32 + lane] = o;
    } else {
        int n = (b - 3 * NBT - 16) * 256 + tid;
        if (n < NN) g_deg[n] = 0;
        if (n < NG) { g_sums[n] = 0.0f; g_cnt[n] = 0.0f; }
    }
}

__global__ void k_embed_count(const int* __restrict__ numbers, const float* __restrict__ emb,
                              const int* __restrict__ src, const int* __restrict__ batch) {
    int i = blockIdx.x * 256 + threadIdx.x;
    if (i < NN * ND) g_x[i] = emb[numbers[i >> 6] * ND + (i & 63)];
    if (i < NE) atomicAdd(&g_deg[src[i]], 1);
    if (i < NN) atomicAdd(&g_cnt[batch[i]], 1.0f);
}
__global__ void k_scanb() {
    __shared__ int s[SB];
    int tid = threadIdx.x;
    int n = blockIdx.x * SB + tid;
    int v = (n < NN) ? g_deg[n] : 0;
    s[tid] = v; __syncthreads();
    for (int o = 1; o < SB; o <<= 1) {
        int t = (tid >= o) ? s[tid - o] : 0;
        __syncthreads();
        s[tid] += t;
        __syncthreads();
    }
    if (n < NN) g_off[n] = s[tid] - v;
    if (tid == SB - 1) g_bsum[blockIdx.x] = s[SB - 1];
}
__global__ void k_scanadd() {
    __shared__ int sred[SB];
    int tid = threadIdx.x;
    int b = blockIdx.x;
    sred[tid] = (tid < b && tid < NB) ? g_bsum[tid] : 0;
    __syncthreads();
    for (int o = SB / 2; o > 0; o >>= 1) {
        if (tid < o) sred[tid] += sred[tid + o];
        __syncthreads();
    }
    int base = sred[0];
    int n = b * SB + tid;
    if (n < NN) {
        int o = g_off[n] + base;
        g_off[n] = o;
        g_pos[n] = o;
    }
    if (b == 0 && tid == 0) g_off[NN] = NE;
}
__global__ void k_scatter(const int* __restrict__ src, const int* __restrict__ tgt,
                          const float* __restrict__ len, const int* __restrict__ numbers) {
    int e = blockIdx.x * 256 + threadIdx.x;
    if (e < NE) {
        int s = src[e];
        int t = tgt[e];
        int r = tabrow_f(len[e]) << 8;
        int p = atomicAdd(&g_pos[s], 1);
        reinterpret_cast<int2*>(g_e12v)[p] = make_int2(t << 8, r);
        reinterpret_cast<int2*>(g_e0v)[p] = make_int2(numbers[t] << 8, r);
    }
}

// general transform: gAq/gBq packed as ((0.5f,0.5f),(log2e*s,log2e*s)) half2 pairs
__global__ void __launch_bounds__(256) k_transform(
    const float* __restrict__ Wf, const float* __restrict__ Ws,
    const float* __restrict__ bf, const float* __restrict__ bs) {
    __shared__ float2 sW[64 * 64];
    __shared__ float  sX[64 * 65];
    int tid = threadIdx.x, lane = tid & 31, w = tid >> 5;
    int n0 = blockIdx.x * 64;
    const u64* sWu = reinterpret_cast<const u64*>(sW);

    for (int e = tid; e < 4096; e += 256) {
        int n = e >> 6, k = e & 63;
        int nn = n0 + n;
        sX[k * 65 + n] = (nn < NN) ? g_x[nn * 64 + k] : 0.0f;
    }
    for (int e = tid; e < 4096; e += 256) {
        int k = e >> 6, j = e & 63;
        sW[e] = make_float2(Wf[k * 64 + j], Ws[k * 64 + j]);
    }
    __syncthreads();
    u64 a[8][2];
    u64 bi0 = pk2(bf[lane], bs[lane]), bi1 = pk2(bf[lane + 32], bs[lane + 32]);
#pragma unroll
    for (int q = 0; q < 8; q++) { a[q][0] = bi0; a[q][1] = bi1; }
#pragma unroll 4
    for (int k = 0; k < 64; k++) {
        u64 w0 = sWu[k * 64 + lane], w1 = sWu[k * 64 + lane + 32];
#pragma unroll
        for (int q = 0; q < 8; q++) {
            u64 xv = pkd(sX[k * 65 + w * 8 + q]);
            a[q][0] = fma2(xv, w0, a[q][0]);
            a[q][1] = fma2(xv, w1, a[q][1]);
        }
    }
#pragma unroll
    for (int q = 0; q < 8; q++) {
        int n = n0 + w * 8 + q;
        if (n < NN) {
            float x0, y0, x1, y1;
            upk2(a[q][0], x0, y0);
            upk2(a[q][1], x1, y1);
            uint2 o;
            o.x = h2u(__floats2half2_rn(0.5f * x0, 0.5f * x1));
            o.y = h2u(__floats2half2_rn(LOG2E * y0, LOG2E * y1));
            g_Aq[n * 32 + lane] = o;
        }
    }
    __syncthreads();
    for (int e = tid; e < 4096; e += 256) {
        int k = e >> 6, j = e & 63;
        sW[e] = make_float2(Wf[(64 + k) * 64 + j], Ws[(64 + k) * 64 + j]);
    }
    __syncthreads();
    u64 z = pk2(0.0f, 0.0f);
#pragma unroll
    for (int q = 0; q < 8; q++) { a[q][0] = z; a[q][1] = z; }
#pragma unroll 4
    for (int k = 0; k < 64; k++) {
        u64 w0 = sWu[k * 64 + lane], w1 = sWu[k * 64 + lane + 32];
#pragma unroll
        for (int q = 0; q < 8; q++) {
            u64 xv = pkd(sX[k * 65 + w * 8 + q]);
            a[q][0] = fma2(xv, w0, a[q][0]);
            a[q][1] = fma2(xv, w1, a[q][1]);
        }
    }
#pragma unroll
    for (int q = 0; q < 8; q++) {
        int n = n0 + w * 8 + q;
        if (n < NN) {
            float x0, y0, x1, y1;
            upk2(a[q][0], x0, y0);
            upk2(a[q][1], x1, y1);
            uint2 o;
            o.x = h2u(__floats2half2_rn(0.5f * x0, 0.5f * x1));
            o.y = h2u(__floats2half2_rn(LOG2E * y0, LOG2E * y1));
            g_Bq[n * 32 + lane] = o;
        }
    }
}

// conv0 edge kernel: grid-stride (~4 nodes/warp), B table in smem
__global__ void __launch_bounds__(256) k_edge0(
    const int* __restrict__ numbers,
    const float* __restrict__ lng, const float* __restrict__ lnb) {
    __shared__ uint2 sB[VOCAB * 32];
    int tid = threadIdx.x, lane = tid & 31, w = tid >> 5;
    for (int e = tid; e < VOCAB * 32; e += 256) sB[e] = g_B0t[e];
    __syncthreads();
    const char* Sb = reinterpret_cast<const char*>(sB) + lane * 8;
    const char* Cb = reinterpret_cast<const char*>(g_tabq) + lane * 8;
    const int2* rec2 = reinterpret_cast<const int2*>(g_e0v);
    float lg0 = lng[lane], lg1 = lng[lane + 32];
    float lb0 = lnb[lane], lb1 = lnb[lane + 32];
    for (int s = blockIdx.x * 8 + w; s < NN; s += EBLK * 8) {
        int e0 = g_off[s], e1 = g_off[s + 1];
        uint2 aa = g_A0q[numbers[s] * 32 + lane];
        float m0 = 0.0f, m1 = 0.0f, p0 = 0.0f, p1 = 0.0f;
        int e = e0;
        if (e < e1 && (e & 1)) {
            int2 r0 = __ldg(&rec2[e]);
            uint2 B0 = *reinterpret_cast<const uint2*>(Sb + r0.x);
            uint2 C0 = __ldg(reinterpret_cast<const uint2*>(Cb + r0.y));
            gate1(aa, B0, C0, m0, m1);
            e++;
        }
#pragma unroll 1
        for (; e + 1 < e1; e += 2) {
            int4 rr = __ldg(&g_e0v[e >> 1]);
            uint2 B0 = *reinterpret_cast<const uint2*>(Sb + rr.x);
            uint2 C0 = __ldg(reinterpret_cast<const uint2*>(Cb + rr.y));
            uint2 B1 = *reinterpret_cast<const uint2*>(Sb + rr.z);
            uint2 C1 = __ldg(reinterpret_cast<const uint2*>(Cb + rr.w));
            gate1(aa, B0, C0, m0, m1);
            gate1(aa, B1, C1, p0, p1);
        }
        if (e < e1) {
            int2 r0 = __ldg(&rec2[e]);
            uint2 B0 = *reinterpret_cast<const uint2*>(Sb + r0.x);
            uint2 C0 = __ldg(reinterpret_cast<const uint2*>(Cb + r0.y));
            gate1(aa, B0, C0, m0, m1);
        }
        m0 = (m0 + p0) * LN2; m1 = (m1 + p1) * LN2;
        float mean = warp_sum(m0 + m1) * (1.0f / 64.0f);
        float d0 = m0 - mean, d1 = m1 - mean;
        float var = warp_sum(d0 * d0 + d1 * d1) * (1.0f / 64.0f);
        float inv = rsqrtf(var + 1e-5f);
        g_x[s * 64 + lane]      += d0 * inv * lg0 + lb0;
        g_x[s * 64 + lane + 32] += d1 * inv * lg1 + lb1;
    }
}

// general edge kernel (convs 1,2): grid-stride (~4 nodes/warp)
__global__ void __launch_bounds__(256) k_edge(int conv,
                                              const float* __restrict__ lng,
                                              const float* __restrict__ lnb) {
    int lane = threadIdx.x & 31, w = threadIdx.x >> 5;
    const char* Bb = reinterpret_cast<const char*>(g_Bq) + lane * 8;
    const char* Cb = reinterpret_cast<const char*>(g_tabq + conv * TROWS * 32) + lane * 8;
    const int2* rec2 = reinterpret_cast<const int2*>(g_e12v);
    float lg0 = lng[lane], lg1 = lng[lane + 32];
    float lb0 = lnb[lane], lb1 = lnb[lane + 32];
    for (int s = blockIdx.x * 8 + w; s < NN; s += EBLK * 8) {
        int e0 = g_off[s], e1 = g_off[s + 1];
        uint2 aa = g_Aq[s * 32 + lane];
        float m0 = 0.0f, m1 = 0.0f, p0 = 0.0f, p1 = 0.0f;
        int e = e0;
        if (e < e1 && (e & 1)) {
            int2 r0 = __ldg(&rec2[e]);
            uint2 B0 = __ldg(reinterpret_cast<const uint2*>(Bb + r0.x));
            uint2 C0 = __ldg(reinterpret_cast<const uint2*>(Cb + r0.y));
            gate1(aa, B0, C0, m0, m1);
            e++;
        }
#pragma unroll 1
        for (; e + 1 < e1; e += 2) {
            int4 rr = __ldg(&g_e12v[e >> 1]);
            uint2 B0 = __ldg(reinterpret_cast<const uint2*>(Bb + rr.x));
            uint2 C0 = __ldg(reinterpret_cast<const uint2*>(Cb + rr.y));
            uint2 B1 = __ldg(reinterpret_cast<const uint2*>(Bb + rr.z));
            uint2 C1 = __ldg(reinterpret_cast<const uint2*>(Cb + rr.w));
            gate1(aa, B0, C0, m0, m1);
            gate1(aa, B1, C1, p0, p1);
        }
        if (e < e1) {
            int2 r0 = __ldg(&rec2[e]);
            uint2 B0 = __ldg(reinterpret_cast<const uint2*>(Bb + r0.x));
            uint2 C0 = __ldg(reinterpret_cast<const uint2*>(Cb + r0.y));
            gate1(aa, B0, C0, m0, m1);
        }
        m0 = (m0 + p0) * LN2; m1 = (m1 + p1) * LN2;
        float mean = warp_sum(m0 + m1) * (1.0f / 64.0f);
        float d0 = m0 - mean, d1 = m1 - mean;
        float var = warp_sum(d0 * d0 + d1 * d1) * (1.0f / 64.0f);
        float inv = rsqrtf(var + 1e-5f);
        g_x[s * 64 + lane]      += d0 * inv * lg0 + lb0;
        g_x[s * 64 + lane + 32] += d1 * inv * lg1 + lb1;
    }
}

// h1 = softplus(LN(x @ W1 + b1))
__global__ void __launch_bounds__(256) k_olp1(
    const float* __restrict__ W1, const float* __restrict__ b1,
    const float* __restrict__ g1, const float* __restrict__ bt1) {
    __shared__ float2 sP[64 * 64];
    int tid = threadIdx.x, lane = tid & 31, w = tid >> 5;
    const u64* sPu = reinterpret_cast<const u64*>(sP);
    for (int e = tid; e < 4096; e += 256) {
        int k = e >> 6, p = e & 63;
        int j0 = (p < 32) ? p : p + 32;
        sP[e] = make_float2(W1[k * 128 + j0], W1[k * 128 + j0 + 32]);
    }
    __syncthreads();
    u64 b01 = pk2(b1[lane], b1[lane + 32]);
    u64 b23 = pk2(b1[lane + 64], b1[lane + 96]);
    for (int it = 0; it < 8; it++) {
        int n = blockIdx.x * 64 + w * 8 + it;
        if (n >= NN) continue;
        float x0 = g_x[n * 64 + lane], x1 = g_x[n * 64 + lane + 32];
        u64 h01 = b01, h23 = b23;
#pragma unroll
        for (int k = 0; k < 64; k++) {
            float xv = __shfl_sync(0xffffffffu, (k < 32) ? x0 : x1, k & 31);
            u64 xv2 = pkd(xv);
            h01 = fma2(xv2, sPu[k * 64 + lane], h01);
            h23 = fma2(xv2, sPu[k * 64 + 32 + lane], h23);
        }
        float h[4];
        upk2(h01, h[0], h[1]);
        upk2(h23, h[2], h[3]);
        float mean = warp_sum(h[0] + h[1] + h[2] + h[3]) * (1.0f / 128.0f);
        float v = 0.0f;
#pragma unroll
        for (int q = 0; q < 4; q++) { h[q] -= mean; v += h[q] * h[q]; }
        float inv = rsqrtf(warp_sum(v) * (1.0f / 128.0f) + 1e-5f);
#pragma unroll
        for (int q = 0; q < 4; q++) {
            float y = h[q] * inv * g1[lane + 32 * q] + bt1[lane + 32 * q];
            g_h1[n * 128 + lane + 32 * q] = softplusf_(y);
        }
    }
}

// h2 = softplus(LN(h1 @ W2 + b2)); e = h2@Wo + bo
__global__ void __launch_bounds__(256) k_olp2(
    const float* __restrict__ W2, const float* __restrict__ b2,
    const float* __restrict__ g2, const float* __restrict__ bt2,
    const float* __restrict__ Wo, const float* __restrict__ bo,
    const int* __restrict__ batch) {
    __shared__ float2 sP[64 * 64];
    int tid = threadIdx.x, lane = tid & 31, w = tid >> 5;
    const u64* sPu = reinterpret_cast<const u64*>(sP);
    int nbase = blockIdx.x * 32 + w * 4;
    u64 a01[4], a23[4];
    float xr[4][4];
    u64 b01 = pk2(b2[lane], b2[lane + 32]);
    u64 b23 = pk2(b2[lane + 64], b2[lane + 96]);
#pragma unroll
    for (int m = 0; m < 4; m++) {
        int n = nbase + m;
        a01[m] = b01; a23[m] = b23;
#pragma unroll
        for (int q = 0; q < 4; q++)
            xr[m][q] = (n < NN) ? g_h1[n * 128 + lane + 32 * q] : 0.0f;
    }
#pragma unroll
    for (int half = 0; half < 2; half++) {
        __syncthreads();
        for (int e = tid; e < 4096; e += 256) {
            int k = e >> 6, p = e & 63;
            int j0 = (p < 32) ? p : p + 32;
            sP[e] = make_float2(W2[(half * 64 + k) * 128 + j0],
                                W2[(half * 64 + k) * 128 + j0 + 32]);
        }
        __syncthreads();
#pragma unroll
        for (int s = 0; s < 2; s++) {
#pragma unroll 8
            for (int k = 0; k < 32; k++) {
                int kk = s * 32 + k;
                u64 w0 = sPu[kk * 64 + lane];
                u64 w1 = sPu[kk * 64 + 32 + lane];
#pragma unroll
                for (int m = 0; m < 4; m++) {
                    float xv = __shfl_sync(0xffffffffu, xr[m][half * 2 + s], k);
                    u64 xv2 = pkd(xv);
                    a01[m] = fma2(xv2, w0, a01[m]);
                    a23[m] = fma2(xv2, w1, a23[m]);
                }
            }
        }
    }
    float wo[4];
#pragma unroll
    for (int q = 0; q < 4; q++) wo[q] = Wo[lane + 32 * q];
    float bov = bo[0];
#pragma unroll
    for (int m = 0; m < 4; m++) {
        int n = nbase + m;
        if (n >= NN) continue;
        float hh[4];
        upk2(a01[m], hh[0], hh[1]);
        upk2(a23[m], hh[2], hh[3]);
        float mean = warp_sum(hh[0] + hh[1] + hh[2] + hh[3]) * (1.0f / 128.0f);
        float v = 0.0f;
#pragma unroll
        for (int q = 0; q < 4; q++) { hh[q] -= mean; v += hh[q] * hh[q]; }
        float inv = rsqrtf(warp_sum(v) * (1.0f / 128.0f) + 1e-5f);
        float e = 0.0f;
#pragma unroll
        for (int q = 0; q < 4; q++) {
            float y = hh[q] * inv * g2[lane + 32 * q] + bt2[lane + 32 * q];
            e += softplusf_(y) * wo[q];
        }
        e = warp_sum(e) + bov;
        if (lane == 0) atomicAdd(&g_sums[batch[n]], e);
    }
}

__global__ void k_fin(float* __restrict__ out) {
    int g = threadIdx.x;
    if (g < NG) out[g] = g_sums[g] / fmaxf(g_cnt[g], 1.0f);
}

extern "C" void kernel_launch(void* const* d_in, const int* in_sizes, int n_in,
                              void* d_out, int out_size) {
    const int*   numbers  = (const int*)d_in[0];
    const int*   eidx     = (const int*)d_in[1];
    const float* elen     = (const float*)d_in[2];
    const int*   batch    = (const int*)d_in[3];
    const float* emb      = (const float*)d_in[4];
    const float* Wf       = (const float*)d_in[5];
    const float* bf       = (const float*)d_in[6];
    const float* Ws       = (const float*)d_in[7];
    const float* bs       = (const float*)d_in[8];
    const float* lng      = (const float*)d_in[9];
    const float* lnb      = (const float*)d_in[10];
    const float* W1       = (const float*)d_in[11];
    const float* b1       = (const float*)d_in[12];
    const float* g1       = (const float*)d_in[13];
    const float* bt1      = (const float*)d_in[14];
    const float* W2       = (const float*)d_in[15];
    const float* b2       = (const float*)d_in[16];
    const float* g2       = (const float*)d_in[17];
    const float* bt2      = (const float*)d_in[18];
    const float* Wo       = (const float*)d_in[19];
    const float* bo       = (const float*)d_in[20];
    float* out = (float*)d_out;

    const int* src = eidx;
    const int* tgt = eidx + NE;

    int pre_blocks = 3 * NBT + 16 + (NN + 255) / 256;
    k_pre<<<pre_blocks, 256>>>(emb, Wf, Ws, bf, bs);
    k_embed_count<<<(NN * ND + 255) / 256, 256>>>(numbers, emb, src, batch);
    k_scanb<<<NB, SB>>>();
    k_scanadd<<<NB, SB>>>();
    k_scatter<<<(NE + 255) / 256, 256>>>(src, tgt, elen, numbers);

    k_edge0<<<EBLK, 256>>>(numbers, lng, lnb);
    for (int i = 1; i < 3; i++) {
        k_transform<<<(NN + 63) / 64, 256>>>(Wf + i * 192 * 64, Ws + i * 192 * 64,
                                             bf + i * 64, bs + i * 64);
        k_edge<<<EBLK, 256>>>(i, lng + i * 64, lnb + i * 64);
    }

    k_olp1<<<(NN + 63) / 64, 256>>>(W1, b1, g1, bt1);
    k_olp2<<<(NN + 31) / 32, 256>>>(W2, b2, g2, bt2, Wo, bo, batch);
    k_fin<<<1, 256>>>(out);
}

// round 17
// speedup vs baseline: 1.1039x; 1.1039x over previous
#include <cuda_runtime.h>
#include <cuda_fp16.h>

#define NN 100000
#define NE 1600000
#define NG 256
#define ND 64
#define NH 128
#define VOCAB 128
#define TROWS 10002
#define TGROUP 16
#define SB 512
#define NB 196
#define NBT ((TROWS + TGROUP - 1) / TGROUP)
#define LOG2E 1.4426950408889634f
#define LN2   0.6931471805599453f

typedef unsigned long long u64;
typedef unsigned int u32;

__device__ float   g_x[NN * ND];
__device__ uint2   g_Aq[NN * 32];
__device__ uint2   g_Bq[NN * 32];
__device__ float   g_h1[NN * NH];
__device__ int     g_deg[NN];
__device__ int     g_off[NN + 1];
__device__ int     g_pos[NN];
__device__ int4    g_e12v[NE / 2];
__device__ int4    g_e0v[NE / 2];
__device__ uint2   g_tabq[3 * TROWS * 32];
__device__ uint2   g_A0q[VOCAB * 32];
__device__ uint2   g_B0t[VOCAB * 32];
__device__ int     g_bsum[256];
__device__ float   g_sums[NG];
__device__ float   g_cnt[NG];

__device__ __forceinline__ u64 pk2(float x, float y) {
    u64 r; asm("mov.b64 %0,{%1,%2};" : "=l"(r) : "f"(x), "f"(y)); return r;
}
__device__ __forceinline__ u64 pkd(float x) { return pk2(x, x); }
__device__ __forceinline__ void upk2(u64 v, float& x, float& y) {
    asm("mov.b64 {%0,%1},%2;" : "=f"(x), "=f"(y) : "l"(v));
}
__device__ __forceinline__ u64 fma2(u64 a, u64 b, u64 c) {
    u64 d; asm("fma.rn.f32x2 %0,%1,%2,%3;" : "=l"(d) : "l"(a), "l"(b), "l"(c)); return d;
}
__device__ __forceinline__ __half2 u2h(u32 u) {
    __half2 h; *reinterpret_cast<u32*>(&h) = u; return h;
}
__device__ __forceinline__ u32 h2u(__half2 h) {
    return *reinterpret_cast<u32*>(&h);
}
__device__ __forceinline__ __half2 tanh_h2(__half2 x) {
    u32 out, in = h2u(x);
    asm("tanh.approx.f16x2 %0,%1;" : "=r"(out) : "r"(in));
    return u2h(out);
}
__device__ __forceinline__ __half2 ex2_h2(__half2 x) {
    u32 out, in = h2u(x);
    asm("ex2.approx.f16x2 %0,%1;" : "=r"(out) : "r"(in));
    return u2h(out);
}
__device__ __forceinline__ float warp_sum(float v) {
#pragma unroll
    for (int o = 16; o > 0; o >>= 1) v += __shfl_xor_sync(0xffffffffu, v, o);
    return v;
}
__device__ __forceinline__ float softplusf_(float x) {
    return fmaxf(x, 0.0f) + __logf(1.0f + __expf(-fabsf(x)));
}
__device__ __forceinline__ int tabrow_f(float dc) {
    int r = __float2int_rn((dc - 1.0f) * 2000.0f);
    return min(max(r, 0), TROWS - 1);
}
// SIMD gate, s-channels pre-scaled by log2e (ln2 restored per node)
__device__ __forceinline__ void gate1(uint2 aaq, uint2 Bv, uint2 Cv,
                                      float& m0, float& m1) {
    const __half2 h05 = __float2half2_rn(0.5f);
    const __half2 c3 = __float2half2_rn(-0.1066667f);
    const __half2 c2 = __float2half2_rn(0.3672997f);
    const __half2 c1 = __float2half2_rn(-0.7033311f);
    const __half2 c0 = __float2half2_rn(1.4426950f);
    const __half2 hz = __float2half2_rn(0.0f);
    __half2 pf = __hadd2(__hadd2(u2h(Bv.x), u2h(Cv.x)), u2h(aaq.x));
    __half2 ps = __hadd2(__hadd2(u2h(Bv.y), u2h(Cv.y)), u2h(aaq.y));
    __half2 sg = __hfma2(tanh_h2(pf), h05, h05);
    __half2 t = ex2_h2(__hneg2(__habs2(ps)));
    __half2 p = __hfma2(t, __hfma2(t, __hfma2(t, c3, c2), c1), c0);
    __half2 sp = __hfma2(t, p, __hmax2(ps, hz));
    float2 pr = __half22float2(__hmul2(sg, sp));
    m0 += pr.x; m1 += pr.y;
}

// ---- fused pre kernel: 3 conv tables + vocab transform + zero-init ----
__global__ void __launch_bounds__(256) k_pre(
    const float* __restrict__ emb,
    const float* __restrict__ Wf, const float* __restrict__ Ws,
    const float* __restrict__ bf, const float* __restrict__ bs) {
    int b = blockIdx.x;
    int tid = threadIdx.x;
    if (b < 3 * NBT) {
        int conv = b / NBT;
        int rbase = (b % NBT) * TGROUP;
        const float* Wef = Wf + conv * 192 * 64 + 128 * 64;
        const float* Wes = Ws + conv * 192 * 64 + 128 * 64;
        __shared__ float4 sW[64 * 32];
        __shared__ float  sw[TGROUP * 64];
        for (int e = tid; e < 2048; e += 256) {
            int k = e >> 5, j = e & 31;
            sW[e] = make_float4(Wef[k * 64 + j], Wes[k * 64 + j],
                                Wef[k * 64 + j + 32], Wes[k * 64 + j + 32]);
        }
        for (int e = tid; e < TGROUP * 64; e += 256) {
            int r = e >> 6, k = e & 63;
            float d = 1.0f + (float)(rbase + r) * 0.0005f;
            float c = 1.0f + (float)k * (5.0f / 63.0f);
            float t = (d - c) * (64.0f / 5.0f);
            sw[e] = __expf(-0.5f * t * t);
        }
        __syncthreads();
#pragma unroll
        for (int it = 0; it < 2; it++) {
            int idx = it * 256 + tid;
            int r = idx >> 5, j = idx & 31;
            int row = rbase + r;
            if (row >= TROWS) continue;
            float c0v = 0.0f, c1v = 0.0f, c2v = 0.0f, c3v = 0.0f;
#pragma unroll 8
            for (int k = 0; k < 64; k++) {
                float wk = sw[r * 64 + k];
                float4 wv = sW[k * 32 + j];
                c0v += wk * wv.x; c1v += wk * wv.y;
                c2v += wk * wv.z; c3v += wk * wv.w;
            }
            uint2 o;
            o.x = h2u(__floats2half2_rn(0.5f * c0v, 0.5f * c2v));
            o.y = h2u(__floats2half2_rn(LOG2E * c1v, LOG2E * c3v));
            g_tabq[(conv * TROWS + row) * 32 + j] = o;
        }
    } else if (b < 3 * NBT + 16) {
        int lane = tid & 31, w = tid >> 5;
        int v = (b - 3 * NBT) * 8 + w;
        if (v >= VOCAB) return;
        float x0 = emb[v * 64 + lane], x1 = emb[v * 64 + lane + 32];
        float af0 = bf[lane], as0 = bs[lane], af1 = bf[lane + 32], as1 = bs[lane + 32];
        float gf0 = 0.0f, gs0 = 0.0f, gf1 = 0.0f, gs1 = 0.0f;
#pragma unroll 8
        for (int k = 0; k < 64; k++) {
            float xv = __shfl_sync(0xffffffffu, (k < 32) ? x0 : x1, k & 31);
            af0 += xv * Wf[k * 64 + lane];
            as0 += xv * Ws[k * 64 + lane];
            af1 += xv * Wf[k * 64 + lane + 32];
            as1 += xv * Ws[k * 64 + lane + 32];
            gf0 += xv * Wf[(64 + k) * 64 + lane];
            gs0 += xv * Ws[(64 + k) * 64 + lane];
            gf1 += xv * Wf[(64 + k) * 64 + lane + 32];
            gs1 += xv * Ws[(64 + k) * 64 + lane + 32];
        }
        uint2 oa;
        oa.x = h2u(__floats2half2_rn(0.5f * af0, 0.5f * af1));
        oa.y = h2u(__floats2half2_rn(LOG2E * as0, LOG2E * as1));
        g_A0q[v * 32 + lane] = oa;
        uint2 o;
        o.x = h2u(__floats2half2_rn(0.5f * gf0, 0.5f * gf1));
        o.y = h2u(__floats2half2_rn(LOG2E * gs0, LOG2E * gs1));
        g_B0t[v * 32 + lane] = o;
    } else {
        int n = (b - 3 * NBT - 16) * 256 + tid;
        if (n < NN) g_deg[n] = 0;
        if (n < NG) { g_sums[n] = 0.0f; g_cnt[n] = 0.0f; }
    }
}

__global__ void k_embed_count(const int* __restrict__ numbers, const float* __restrict__ emb,
                              const int* __restrict__ src, const int* __restrict__ batch) {
    int i = blockIdx.x * 256 + threadIdx.x;
    if (i < NN * ND) g_x[i] = emb[numbers[i >> 6] * ND + (i & 63)];
    if (i < NE) atomicAdd(&g_deg[src[i]], 1);
    if (i < NN) atomicAdd(&g_cnt[batch[i]], 1.0f);
}
__global__ void k_scanb() {
    __shared__ int s[SB];
    int tid = threadIdx.x;
    int n = blockIdx.x * SB + tid;
    int v = (n < NN) ? g_deg[n] : 0;
    s[tid] = v; __syncthreads();
    for (int o = 1; o < SB; o <<= 1) {
        int t = (tid >= o) ? s[tid - o] : 0;
        __syncthreads();
        s[tid] += t;
        __syncthreads();
    }
    if (n < NN) g_off[n] = s[tid] - v;
    if (tid == SB - 1) g_bsum[blockIdx.x] = s[SB - 1];
}
__global__ void k_scanadd() {
    __shared__ int sred[SB];
    int tid = threadIdx.x;
    int b = blockIdx.x;
    sred[tid] = (tid < b && tid < NB) ? g_bsum[tid] : 0;
    __syncthreads();
    for (int o = SB / 2; o > 0; o >>= 1) {
        if (tid < o) sred[tid] += sred[tid + o];
        __syncthreads();
    }
    int base = sred[0];
    int n = b * SB + tid;
    if (n < NN) {
        int o = g_off[n] + base;
        g_off[n] = o;
        g_pos[n] = o;
    }
    if (b == 0 && tid == 0) g_off[NN] = NE;
}
__global__ void k_scatter(const int* __restrict__ src, const int* __restrict__ tgt,
                          const float* __restrict__ len, const int* __restrict__ numbers) {
    int e = blockIdx.x * 256 + threadIdx.x;
    if (e < NE) {
        int s = src[e];
        int t = tgt[e];
        int r = tabrow_f(len[e]) << 8;
        int p = atomicAdd(&g_pos[s], 1);
        reinterpret_cast<int2*>(g_e12v)[p] = make_int2(t << 8, r);
        reinterpret_cast<int2*>(g_e0v)[p] = make_int2(numbers[t] << 8, r);
    }
}

// general transform: gAq/gBq packed as ((0.5f,0.5f),(log2e*s,log2e*s)) half2 pairs
__global__ void __launch_bounds__(256) k_transform(
    const float* __restrict__ Wf, const float* __restrict__ Ws,
    const float* __restrict__ bf, const float* __restrict__ bs) {
    __shared__ float2 sW[64 * 64];
    __shared__ float  sX[64 * 65];
    int tid = threadIdx.x, lane = tid & 31, w = tid >> 5;
    int n0 = blockIdx.x * 64;
    const u64* sWu = reinterpret_cast<const u64*>(sW);

    for (int e = tid; e < 4096; e += 256) {
        int n = e >> 6, k = e & 63;
        int nn = n0 + n;
        sX[k * 65 + n] = (nn < NN) ? g_x[nn * 64 + k] : 0.0f;
    }
    for (int e = tid; e < 4096; e += 256) {
        int k = e >> 6, j = e & 63;
        sW[e] = make_float2(Wf[k * 64 + j], Ws[k * 64 + j]);
    }
    __syncthreads();
    u64 a[8][2];
    u64 bi0 = pk2(bf[lane], bs[lane]), bi1 = pk2(bf[lane + 32], bs[lane + 32]);
#pragma unroll
    for (int q = 0; q < 8; q++) { a[q][0] = bi0; a[q][1] = bi1; }
#pragma unroll 4
    for (int k = 0; k < 64; k++) {
        u64 w0 = sWu[k * 64 + lane], w1 = sWu[k * 64 + lane + 32];
#pragma unroll
        for (int q = 0; q < 8; q++) {
            u64 xv = pkd(sX[k * 65 + w * 8 + q]);
            a[q][0] = fma2(xv, w0, a[q][0]);
            a[q][1] = fma2(xv, w1, a[q][1]);
        }
    }
#pragma unroll
    for (int q = 0; q < 8; q++) {
        int n = n0 + w * 8 + q;
        if (n < NN) {
            float x0, y0, x1, y1;
            upk2(a[q][0], x0, y0);
            upk2(a[q][1], x1, y1);
            uint2 o;
            o.x = h2u(__floats2half2_rn(0.5f * x0, 0.5f * x1));
            o.y = h2u(__floats2half2_rn(LOG2E * y0, LOG2E * y1));
            g_Aq[n * 32 + lane] = o;
        }
    }
    __syncthreads();
    for (int e = tid; e < 4096; e += 256) {
        int k = e >> 6, j = e & 63;
        sW[e] = make_float2(Wf[(64 + k) * 64 + j], Ws[(64 + k) * 64 + j]);
    }
    __syncthreads();
    u64 z = pk2(0.0f, 0.0f);
#pragma unroll
    for (int q = 0; q < 8; q++) { a[q][0] = z; a[q][1] = z; }
#pragma unroll 4
    for (int k = 0; k < 64; k++) {
        u64 w0 = sWu[k * 64 + lane], w1 = sWu[k * 64 + lane + 32];
#pragma unroll
        for (int q = 0; q < 8; q++) {
            u64 xv = pkd(sX[k * 65 + w * 8 + q]);
            a[q][0] = fma2(xv, w0, a[q][0]);
            a[q][1] = fma2(xv, w1, a[q][1]);
        }
    }
#pragma unroll
    for (int q = 0; q < 8; q++) {
        int n = n0 + w * 8 + q;
        if (n < NN) {
            float x0, y0, x1, y1;
            upk2(a[q][0], x0, y0);
            upk2(a[q][1], x1, y1);
            uint2 o;
            o.x = h2u(__floats2half2_rn(0.5f * x0, 0.5f * x1));
            o.y = h2u(__floats2half2_rn(LOG2E * y0, LOG2E * y1));
            g_Bq[n * 32 + lane] = o;
        }
    }
}

// conv0 edge kernel: one node/warp, B table via __ldg (L1-resident 32KB)
__global__ void __launch_bounds__(256) k_edge0(
    const int* __restrict__ numbers,
    const float* __restrict__ lng, const float* __restrict__ lnb) {
    int lane = threadIdx.x & 31, w = threadIdx.x >> 5;
    int s = blockIdx.x * 8 + w;
    if (s >= NN) return;
    const char* Sb = reinterpret_cast<const char*>(g_B0t) + lane * 8;
    const char* Cb = reinterpret_cast<const char*>(g_tabq) + lane * 8;
    const int2* rec2 = reinterpret_cast<const int2*>(g_e0v);
    int e0 = g_off[s], e1 = g_off[s + 1];
    uint2 aa = g_A0q[numbers[s] * 32 + lane];
    float m0 = 0.0f, m1 = 0.0f, p0 = 0.0f, p1 = 0.0f;
    int e = e0;
    if (e < e1 && (e & 1)) {
        int2 r0 = __ldg(&rec2[e]);
        uint2 B0 = __ldg(reinterpret_cast<const uint2*>(Sb + r0.x));
        uint2 C0 = __ldg(reinterpret_cast<const uint2*>(Cb + r0.y));
        gate1(aa, B0, C0, m0, m1);
        e++;
    }
#pragma unroll 1
    for (; e + 1 < e1; e += 2) {
        int4 rr = __ldg(&g_e0v[e >> 1]);
        uint2 B0 = __ldg(reinterpret_cast<const uint2*>(Sb + rr.x));
        uint2 C0 = __ldg(reinterpret_cast<const uint2*>(Cb + rr.y));
        uint2 B1 = __ldg(reinterpret_cast<const uint2*>(Sb + rr.z));
        uint2 C1 = __ldg(reinterpret_cast<const uint2*>(Cb + rr.w));
        gate1(aa, B0, C0, m0, m1);
        gate1(aa, B1, C1, p0, p1);
    }
    if (e < e1) {
        int2 r0 = __ldg(&rec2[e]);
        uint2 B0 = __ldg(reinterpret_cast<const uint2*>(Sb + r0.x));
        uint2 C0 = __ldg(reinterpret_cast<const uint2*>(Cb + r0.y));
        gate1(aa, B0, C0, m0, m1);
    }
    m0 = (m0 + p0) * LN2; m1 = (m1 + p1) * LN2;
    float mean = warp_sum(m0 + m1) * (1.0f / 64.0f);
    float d0 = m0 - mean, d1 = m1 - mean;
    float var = warp_sum(d0 * d0 + d1 * d1) * (1.0f / 64.0f);
    float inv = rsqrtf(var + 1e-5f);
    g_x[s * 64 + lane]      += d0 * inv * lng[lane]      + lnb[lane];
    g_x[s * 64 + lane + 32] += d1 * inv * lng[lane + 32] + lnb[lane + 32];
}

// general edge kernel (convs 1,2): one node/warp, byte-offset records
__global__ void __launch_bounds__(256) k_edge(int conv,
                                              const float* __restrict__ lng,
                                              const float* __restrict__ lnb) {
    int lane = threadIdx.x & 31, w = threadIdx.x >> 5;
    int s = blockIdx.x * 8 + w;
    if (s >= NN) return;
    const char* Bb = reinterpret_cast<const char*>(g_Bq) + lane * 8;
    const char* Cb = reinterpret_cast<const char*>(g_tabq + conv * TROWS * 32) + lane * 8;
    const int2* rec2 = reinterpret_cast<const int2*>(g_e12v);
    int e0 = g_off[s], e1 = g_off[s + 1];
    uint2 aa = g_Aq[s * 32 + lane];
    float m0 = 0.0f, m1 = 0.0f, p0 = 0.0f, p1 = 0.0f;
    int e = e0;
    if (e < e1 && (e & 1)) {
        int2 r0 = __ldg(&rec2[e]);
        uint2 B0 = __ldg(reinterpret_cast<const uint2*>(Bb + r0.x));
        uint2 C0 = __ldg(reinterpret_cast<const uint2*>(Cb + r0.y));
        gate1(aa, B0, C0, m0, m1);
        e++;
    }
#pragma unroll 1
    for (; e + 1 < e1; e += 2) {
        int4 rr = __ldg(&g_e12v[e >> 1]);
        uint2 B0 = __ldg(reinterpret_cast<const uint2*>(Bb + rr.x));
        uint2 C0 = __ldg(reinterpret_cast<const uint2*>(Cb + rr.y));
        uint2 B1 = __ldg(reinterpret_cast<const uint2*>(Bb + rr.z));
        uint2 C1 = __ldg(reinterpret_cast<const uint2*>(Cb + rr.w));
        gate1(aa, B0, C0, m0, m1);
        gate1(aa, B1, C1, p0, p1);
    }
    if (e < e1) {
        int2 r0 = __ldg(&rec2[e]);
        uint2 B0 = __ldg(reinterpret_cast<const uint2*>(Bb + r0.x));
        uint2 C0 = __ldg(reinterpret_cast<const uint2*>(Cb + r0.y));
        gate1(aa, B0, C0, m0, m1);
    }
    m0 = (m0 + p0) * LN2; m1 = (m1 + p1) * LN2;
    float mean = warp_sum(m0 + m1) * (1.0f / 64.0f);
    float d0 = m0 - mean, d1 = m1 - mean;
    float var = warp_sum(d0 * d0 + d1 * d1) * (1.0f / 64.0f);
    float inv = rsqrtf(var + 1e-5f);
    g_x[s * 64 + lane]      += d0 * inv * lng[lane]      + lnb[lane];
    g_x[s * 64 + lane + 32] += d1 * inv * lng[lane + 32] + lnb[lane + 32];
}

// h1 = softplus(LN(x @ W1 + b1))
__global__ void __launch_bounds__(256) k_olp1(
    const float* __restrict__ W1, const float* __restrict__ b1,
    const float* __restrict__ g1, const float* __restrict__ bt1) {
    __shared__ float2 sP[64 * 64];
    int tid = threadIdx.x, lane = tid & 31, w = tid >> 5;
    const u64* sPu = reinterpret_cast<const u64*>(sP);
    for (int e = tid; e < 4096; e += 256) {
        int k = e >> 6, p = e & 63;
        int j0 = (p < 32) ? p : p + 32;
        sP[e] = make_float2(W1[k * 128 + j0], W1[k * 128 + j0 + 32]);
    }
    __syncthreads();
    u64 b01 = pk2(b1[lane], b1[lane + 32]);
    u64 b23 = pk2(b1[lane + 64], b1[lane + 96]);
    for (int it = 0; it < 8; it++) {
        int n = blockIdx.x * 64 + w * 8 + it;
        if (n >= NN) continue;
        float x0 = g_x[n * 64 + lane], x1 = g_x[n * 64 + lane + 32];
        u64 h01 = b01, h23 = b23;
#pragma unroll
        for (int k = 0; k < 64; k++) {
            float xv = __shfl_sync(0xffffffffu, (k < 32) ? x0 : x1, k & 31);
            u64 xv2 = pkd(xv);
            h01 = fma2(xv2, sPu[k * 64 + lane], h01);
            h23 = fma2(xv2, sPu[k * 64 + 32 + lane], h23);
        }
        float h[4];
        upk2(h01, h[0], h[1]);
        upk2(h23, h[2], h[3]);
        float mean = warp_sum(h[0] + h[1] + h[2] + h[3]) * (1.0f / 128.0f);
        float v = 0.0f;
#pragma unroll
        for (int q = 0; q < 4; q++) { h[q] -= mean; v += h[q] * h[q]; }
        float inv = rsqrtf(warp_sum(v) * (1.0f / 128.0f) + 1e-5f);
#pragma unroll
        for (int q = 0; q < 4; q++) {
            float y = h[q] * inv * g1[lane + 32 * q] + bt1[lane + 32 * q];
            g_h1[n * 128 + lane + 32 * q] = softplusf_(y);
        }
    }
}

// h2 = softplus(LN(h1 @ W2 + b2)); e = h2@Wo + bo
__global__ void __launch_bounds__(256) k_olp2(
    const float* __restrict__ W2, const float* __restrict__ b2,
    const float* __restrict__ g2, const float* __restrict__ bt2,
    const float* __restrict__ Wo, const float* __restrict__ bo,
    const int* __restrict__ batch) {
    __shared__ float2 sP[64 * 64];
    int tid = threadIdx.x, lane = tid & 31, w = tid >> 5;
    const u64* sPu = reinterpret_cast<const u64*>(sP);
    int nbase = blockIdx.x * 32 + w * 4;
    u64 a01[4], a23[4];
    float xr[4][4];
    u64 b01 = pk2(b2[lane], b2[lane + 32]);
    u64 b23 = pk2(b2[lane + 64], b2[lane + 96]);
#pragma unroll
    for (int m = 0; m < 4; m++) {
        int n = nbase + m;
        a01[m] = b01; a23[m] = b23;
#pragma unroll
        for (int q = 0; q < 4; q++)
            xr[m][q] = (n < NN) ? g_h1[n * 128 + lane + 32 * q] : 0.0f;
    }
#pragma unroll
    for (int half = 0; half < 2; half++) {
        __syncthreads();
        for (int e = tid; e < 4096; e += 256) {
            int k = e >> 6, p = e & 63;
            int j0 = (p < 32) ? p : p + 32;
            sP[e] = make_float2(W2[(half * 64 + k) * 128 + j0],
                                W2[(half * 64 + k) * 128 + j0 + 32]);
        }
        __syncthreads();
#pragma unroll
        for (int s = 0; s < 2; s++) {
#pragma unroll 8
            for (int k = 0; k < 32; k++) {
                int kk = s * 32 + k;
                u64 w0 = sPu[kk * 64 + lane];
                u64 w1 = sPu[kk * 64 + 32 + lane];
#pragma unroll
                for (int m = 0; m < 4; m++) {
                    float xv = __shfl_sync(0xffffffffu, xr[m][half * 2 + s], k);
                    u64 xv2 = pkd(xv);
                    a01[m] = fma2(xv2, w0, a01[m]);
                    a23[m] = fma2(xv2, w1, a23[m]);
                }
            }
        }
    }
    float wo[4];
#pragma unroll
    for (int q = 0; q < 4; q++) wo[q] = Wo[lane + 32 * q];
    float bov = bo[0];
#pragma unroll
    for (int m = 0; m < 4; m++) {
        int n = nbase + m;
        if (n >= NN) continue;
        float hh[4];
        upk2(a01[m], hh[0], hh[1]);
        upk2(a23[m], hh[2], hh[3]);
        float mean = warp_sum(hh[0] + hh[1] + hh[2] + hh[3]) * (1.0f / 128.0f);
        float v = 0.0f;
#pragma unroll
        for (int q = 0; q < 4; q++) { hh[q] -= mean; v += hh[q] * hh[q]; }
        float inv = rsqrtf(warp_sum(v) * (1.0f / 128.0f) + 1e-5f);
        float e = 0.0f;
#pragma unroll
        for (int q = 0; q < 4; q++) {
            float y = hh[q] * inv * g2[lane + 32 * q] + bt2[lane + 32 * q];
            e += softplusf_(y) * wo[q];
        }
        e = warp_sum(e) + bov;
        if (lane == 0) atomicAdd(&g_sums[batch[n]], e);
    }
}

__global__ void k_fin(float* __restrict__ out) {
    int g = threadIdx.x;
    if (g < NG) out[g] = g_sums[g] / fmaxf(g_cnt[g], 1.0f);
}

extern "C" void kernel_launch(void* const* d_in, const int* in_sizes, int n_in,
                              void* d_out, int out_size) {
    const int*   numbers  = (const int*)d_in[0];
    const int*   eidx     = (const int*)d_in[1];
    const float* elen     = (const float*)d_in[2];
    const int*   batch    = (const int*)d_in[3];
    const float* emb      = (const float*)d_in[4];
    const float* Wf       = (const float*)d_in[5];
    const float* bf       = (const float*)d_in[6];
    const float* Ws       = (const float*)d_in[7];
    const float* bs       = (const float*)d_in[8];
    const float* lng      = (const float*)d_in[9];
    const float* lnb      = (const float*)d_in[10];
    const float* W1       = (const float*)d_in[11];
    const float* b1       = (const float*)d_in[12];
    const float* g1       = (const float*)d_in[13];
    const float* bt1      = (const float*)d_in[14];
    const float* W2       = (const float*)d_in[15];
    const float* b2       = (const float*)d_in[16];
    const float* g2       = (const float*)d_in[17];
    const float* bt2      = (const float*)d_in[18];
    const float* Wo       = (const float*)d_in[19];
    const float* bo       = (const float*)d_in[20];
    float* out = (float*)d_out;

    const int* src = eidx;
    const int* tgt = eidx + NE;

    int pre_blocks = 3 * NBT + 16 + (NN + 255) / 256;
    k_pre<<<pre_blocks, 256>>>(emb, Wf, Ws, bf, bs);
    k_embed_count<<<(NN * ND + 255) / 256, 256>>>(numbers, emb, src, batch);
    k_scanb<<<NB, SB>>>();
    k_scanadd<<<NB, SB>>>();
    k_scatter<<<(NE + 255) / 256, 256>>>(src, tgt, elen, numbers);

    k_edge0<<<(NN + 7) / 8, 256>>>(numbers, lng, lnb);
    for (int i = 1; i < 3; i++) {
        k_transform<<<(NN + 63) / 64, 256>>>(Wf + i * 192 * 64, Ws + i * 192 * 64,
                                             bf + i * 64, bs + i * 64);
        k_edge<<<(NN + 7) / 8, 256>>>(i, lng + i * 64, lnb + i * 64);
    }

    k_olp1<<<(NN + 63) / 64, 256>>>(W1, b1, g1, bt1);
    k_olp2<<<(NN + 31) / 32, 256>>>(W2, b2, g2, bt2, Wo, bo, batch);
    k_fin<<<1, 256>>>(out);
}